// round 6
// baseline (speedup 1.0000x reference)
#include <cuda_runtime.h>
#include <cuda_bf16.h>
#include <math.h>

// Problem constants (fixed by the reference)
#define BB 8
#define SS 4096
#define DD 1024
#define HH 16
#define HD 64
#define NR 32
#define NFREQ 32            // HD/2
#define ROWS (BB * SS * HH) // 524288

// Static device scratch (no runtime allocation allowed)
__device__ float2 g_cs[SS * NFREQ];   // interleaved (cos, sin), 1 MB
__device__ int    g_rot_i[NR];
__device__ int    g_rot_j[NR];
__device__ float  g_rot_c[NR];
__device__ float  g_rot_s[NR];
__device__ int    g_not_identity;

// ---------------------------------------------------------------------------
// Setup 1 (1 tiny block): reset flag + rotation params
__global__ void k_setup1(const float* __restrict__ thetas,
                         const float* __restrict__ r_pairs,
                         const float* __restrict__ theta_scale) {
    int t = threadIdx.x;
    if (t == 0) g_not_identity = 0;
    if (t < NR) {
        g_rot_i[t] = (int)r_pairs[2 * t];
        g_rot_j[t] = (int)r_pairs[2 * t + 1];
        float th = thetas[t] * theta_scale[0];
        float sv, cv;
        sincosf(th, &sv, &cv);
        g_rot_c[t] = cv;
        g_rot_s[t] = sv;
    }
}

// Setup 2: RoPE cos/sin table (accurate range reduction) + identity check
__global__ void k_setup2(const float* __restrict__ inv_freq,
                         const float* __restrict__ rm) {
    int e = blockIdx.x * blockDim.x + threadIdx.x;
    if (e < HD * HD) {
        float expect = ((e / HD) == (e % HD)) ? 1.0f : 0.0f;
        if (rm[e] != expect) g_not_identity = 1; // benign race
    }
    if (e >= SS * NFREQ) return;
    int s = e >> 5;
    int k = e & 31;
    float af = (float)s * inv_freq[k];       // f32 product, matches reference
    const double TWO_PI  = 6.283185307179586476925286766559;
    const double INV2PI  = 0.15915494309189533576888376337251;
    double a = (double)af;
    double n = rint(a * INV2PI);
    double r = fma(-n, TWO_PI, a);           // r in [-pi, pi]
    float sv, cv;
    sincosf((float)r, &sv, &cv);
    g_cs[e] = make_float2(cv, sv);
}

// ---------------------------------------------------------------------------
// XOR component permute: w[f] = v[f ^ p], p in [0,4)
__device__ __forceinline__ float4 xperm(float4 v, int p) {
    float4 w = v;
    if (p & 1) w = make_float4(w.y, w.x, w.w, w.z);
    if (p & 2) w = make_float4(w.z, w.w, w.x, w.y);
    return w;
}

// Main kernel: 128 threads/block, block covers 128 contiguous rows (32 KB).
// Shared layout: element (row, col) lives at buf[row*64 + (col ^ (row & 31))].
//  - rotation phase (per-thread scalar): bank = (col&31)^(row&31) -> conflict-free
//  - staging / epilogue: aligned 16B/32B blocks, component-XOR permuted
#define TPB 128

__global__ void __launch_bounds__(TPB, 6)
k_main(const float* __restrict__ x,
       const float* __restrict__ r_matrix,
       float* __restrict__ out) {
    __shared__ float  buf[TPB * HD];      // 32 KB, swizzled
    __shared__ float2 cs[8][NFREQ];       // 2 KB: 8 s-positions per block
    __shared__ float  rc[NR], rs[NR];
    __shared__ int    ri[NR], rj[NR];

    const int tid = threadIdx.x;
    const int bid = blockIdx.x;
    const long long elem_base = (long long)bid * (TPB * HD);

    // rotation params -> smem
    if (tid < NR) {
        ri[tid] = g_rot_i[tid];
        rj[tid] = g_rot_j[tid];
        rc[tid] = g_rot_c[tid];
        rs[tid] = g_rot_s[tid];
    }
    // cos/sin table for this block's 8 s-positions
    {
        int sg0 = bid * 8; // first (b*S + s) index; s = sg0 & (SS-1)
        #pragma unroll
        for (int e = tid; e < 8 * NFREQ; e += TPB) {
            int l = e >> 5, k = e & 31;
            int s = (sg0 + l) & (SS - 1);
            cs[l][k] = g_cs[s * NFREQ + k];
        }
    }

    // --- stage input: coalesced float4 -> swizzled smem (STS.128) ---
    const float4* __restrict__ xin = reinterpret_cast<const float4*>(x) + (elem_base >> 2);
    float4* __restrict__ buf4 = reinterpret_cast<float4*>(buf);
    #pragma unroll
    for (int it = 0; it < 16; it++) {
        int g   = tid + it * TPB;       // float4 index within block chunk
        float4 v = xin[g];
        int row = g >> 4;
        int c4  = (g & 15) << 2;
        int r   = row & 31;
        int base = row * 16 + ((c4 ^ (r & 28)) >> 2); // float4 units
        buf4[base] = xperm(v, r & 3);
    }
    __syncthreads();

    // --- 32 sequential Givens rotations (own row, conflict-free scalar) ---
    {
        const int rbase = tid * HD;
        const int rsw   = tid & 31;
        for (int r = 0; r < NR; r++) {
            int i = ri[r], j = rj[r];
            float c = rc[r], s = rs[r];
            float* pi = &buf[rbase + (i ^ rsw)];
            float* pj = &buf[rbase + (j ^ rsw)];
            float xi = *pi;
            float xj = *pj;
            if (i == j) {
                *pi = xi * c;
            } else {
                *pi = fmaf(xj, s, xi * c);
                *pj = fmaf(xj, c, -xi * s);
            }
        }
    }

    // --- cold generic path: y = y @ r_matrix (skipped when identity) ---
    if (g_not_identity) {
        const int rbase = tid * HD;
        const int rsw   = tid & 31;
        float zl[HD]; // local memory (unroll 1) -> no hot-path registers
        #pragma unroll 1
        for (int c = 0; c < HD; c++) {
            float acc = 0.0f;
            #pragma unroll 1
            for (int k = 0; k < HD; k++)
                acc = fmaf(buf[rbase + (k ^ rsw)], __ldg(&r_matrix[k * HD + c]), acc);
            zl[c] = acc;
        }
        #pragma unroll 1
        for (int c = 0; c < HD; c++)
            buf[rbase + (c ^ rsw)] = zl[c];
    }
    __syncthreads();

    // --- fused RoPE + output stage: read aligned 32B y-blocks, apply cos/sin,
    //     write coalesced float4 to global ---
    float4* __restrict__ op = reinterpret_cast<float4*>(out) + (elem_base >> 2);
    #pragma unroll
    for (int it = 0; it < 16; it++) {
        int g   = tid + it * TPB;
        int row = g >> 4;
        int c4  = (g & 15) << 2;        // output columns c4..c4+3
        int r   = row & 31;
        int k0  = c4 & 31;              // freq index base (0..28)
        int b8  = 2 * k0;               // logical y block start (8 floats)
        int phys = row * 16 + ((b8 ^ (r & 24)) >> 2); // float4 units
        float4 q0 = buf4[phys];
        float4 q1 = buf4[phys + 1];
        int rl = r & 7;
        float4 a = (rl & 4) ? q1 : q0;
        float4 b = (rl & 4) ? q0 : q1;
        int p = rl & 3;
        float4 ya = xperm(a, p);        // logical y[b8+0 .. b8+3]
        float4 yb = xperm(b, p);        // logical y[b8+4 .. b8+7]

        int l = row >> 4;               // s-position within block (0..7)
        float2 cs0 = cs[l][k0 + 0];
        float2 cs1 = cs[l][k0 + 1];
        float2 cs2 = cs[l][k0 + 2];
        float2 cs3 = cs[l][k0 + 3];

        float4 o;
        if (c4 < 32) { // low half: y0*c - y1*s
            o.x = fmaf(ya.x, cs0.x, -ya.y * cs0.y);
            o.y = fmaf(ya.z, cs1.x, -ya.w * cs1.y);
            o.z = fmaf(yb.x, cs2.x, -yb.y * cs2.y);
            o.w = fmaf(yb.z, cs3.x, -yb.w * cs3.y);
        } else {       // high half: y0*s + y1*c
            o.x = fmaf(ya.x, cs0.y, ya.y * cs0.x);
            o.y = fmaf(ya.z, cs1.y, ya.w * cs1.x);
            o.z = fmaf(yb.x, cs2.y, yb.y * cs2.x);
            o.w = fmaf(yb.z, cs3.y, yb.w * cs3.x);
        }
        op[g] = o;
    }
}

// ---------------------------------------------------------------------------
extern "C" void kernel_launch(void* const* d_in, const int* in_sizes, int n_in,
                              void* d_out, int out_size) {
    const float* x        = (const float*)d_in[0];
    const float* thetas   = (const float*)d_in[1];
    const float* r_pairs  = (const float*)d_in[2];
    const float* t_scale  = (const float*)d_in[3];
    // d_in[4] = n_rots_scale (unused by the reference)
    const float* r_matrix = (const float*)d_in[5];
    const float* inv_freq = (const float*)d_in[6];
    float* out = (float*)d_out;

    k_setup1<<<1, 32>>>(thetas, r_pairs, t_scale);
    k_setup2<<<(SS * NFREQ + 255) / 256, 256>>>(inv_freq, r_matrix);

    int nblocks = ROWS / TPB; // 4096
    k_main<<<nblocks, TPB>>>(x, r_matrix, out);
}